// round 16
// baseline (speedup 1.0000x reference)
#include <cuda_runtime.h>
#include <cstdint>
#include <mma.h>
#include <cuda_fp16.h>
#include <math.h>

using namespace nvcuda;

#define H        128
#define BM       64       // rows per tile
#define XLH      136      // half leading dim for input tiles (8-half pad)
#define WLH      136      // half leading dim for weights
#define XLD      132      // float leading dim for accum buffer
#define NTHREADS 1024     // 16 consumer warps + 16 producer warps
#define NSM      152

#define XH_BYTES (BM * XLH * 2)          // 17408
#define YF_BYTES (BM * XLD * 4)          // 33792
#define WH_BYTES (H * WLH * 2)           // 34816
#define SMEM_BYTES (2 * XH_BYTES + 2 * YF_BYTES + 2 * WH_BYTES)   // 172032

// ---------------- scratch (fp16 mirrors + fp16 A) ----------------
#define MAX_NODES 100000
__device__ __half g_xh_src[(size_t)MAX_NODES * H];
__device__ __half g_xh_dst[(size_t)MAX_NODES * H];
__device__ __half g_A_src[(size_t)MAX_NODES * H];
__device__ __half g_A_dst[(size_t)MAX_NODES * H];

// ---------------- named barriers (1024 = full CTA) ----------------
#define BSYNC(id)  asm volatile("bar.sync %0, 1024;"   :: "r"(id) : "memory")
#define BARR(id)   asm volatile("bar.arrive %0, 1024;" :: "r"(id) : "memory")

// ---------------- helpers ----------------
__device__ __forceinline__ void pf_l2(const void* p)
{
    asm volatile("prefetch.global.L2 [%0];" :: "l"(p));
}

struct alignas(8) h4 { __half2 a, b; };

__device__ __forceinline__ h4 ldg_h4(const h4* p)
{
    uint2 u = __ldg((const uint2*)p);
    h4 t;
    t.a = *(__half2*)&u.x;
    t.b = *(__half2*)&u.y;
    return t;
}

__device__ __forceinline__ h4 f4_to_h4(float4 v)
{
    h4 t;
    t.a = __floats2half2_rn(v.x, v.y);
    t.b = __floats2half2_rn(v.z, v.w);
    return t;
}
__device__ __forceinline__ float4 h4_to_f4(h4 t)
{
    float2 lo = __half22float2(t.a), hi = __half22float2(t.b);
    return make_float4(lo.x, lo.y, hi.x, hi.y);
}
__device__ __forceinline__ void st_half4(__half* p, float4 v)
{
    *(h4*)p = f4_to_h4(v);
}

// convert a 128x128 float weight matrix (row stride `stride`) to half in smem
__device__ __forceinline__ void load_wh(
    __half* __restrict__ Wh, const float* __restrict__ Wg, int stride, int tid)
{
    for (int idx = tid; idx < H * 32; idx += NTHREADS) {
        int j = idx >> 5, k4 = idx & 31;
        float4 v = __ldg((const float4*)(Wg + (size_t)j * stride) + k4);
        st_half4(Wh + j * WLH + k4 * 4, v);
    }
}

// 16 consumer warps on a 64x128 tile: warp w -> rows [wm,wm+16), cols [wn,wn+32)
__device__ __forceinline__ void gemm64h(
    const __half* __restrict__ Xs, const __half* __restrict__ Ws,
    wmma::fragment<wmma::accumulator, 16, 16, 16, float> (&acc)[2],
    int wm, int wn)
{
    #pragma unroll
    for (int j = 0; j < 2; j++)
        wmma::fill_fragment(acc[j], 0.0f);

    #pragma unroll
    for (int k0 = 0; k0 < H; k0 += 16) {
        wmma::fragment<wmma::matrix_a, 16, 16, 16, __half, wmma::row_major> a;
        wmma::fragment<wmma::matrix_b, 16, 16, 16, __half, wmma::col_major> b[2];
        wmma::load_matrix_sync(a, Xs + wm * XLH + k0, XLH);
        #pragma unroll
        for (int j = 0; j < 2; j++)
            wmma::load_matrix_sync(b[j], Ws + (wn + j * 16) * WLH + k0, WLH);
        #pragma unroll
        for (int j = 0; j < 2; j++)
            wmma::mma_sync(acc[j], a, b[j], acc[j]);
    }
}

__device__ __forceinline__ void store_accf(
    float* __restrict__ Yf,
    wmma::fragment<wmma::accumulator, 16, 16, 16, float> (&acc)[2],
    int wm, int wn)
{
    #pragma unroll
    for (int j = 0; j < 2; j++)
        wmma::store_matrix_sync(Yf + wm * XLD + wn + j * 16, acc[j], XLD,
                                wmma::mem_row_major);
}

// =====================================================================
// NODE kernel: A[n] = (leakyrelu(x @ Wenc^T + benc)) @ W1slab^T
// Also emits fp16 mirrors of x; A stored as fp16. Grid-split halves.
// Warps 0-15 tensor, 16-31 memory.
// =====================================================================
__global__ void __launch_bounds__(NTHREADS, 1)
node_kernel(const float* __restrict__ x_src, const float* __restrict__ x_dst,
            const float* __restrict__ Wp, const float* __restrict__ bp,
            const float* __restrict__ Wc, const float* __restrict__ bc,
            const float* __restrict__ W1,
            __half* __restrict__ xh_src, __half* __restrict__ xh_dst,
            __half* __restrict__ A_src, __half* __restrict__ A_dst,
            int n_nodes, int ntiles)
{
    extern __shared__ char smem[];
    __half* Xh[2] = { (__half*)smem, (__half*)(smem + XH_BYTES) };
    float*  Yf[2] = { (float*)(smem + 2 * XH_BYTES),
                      (float*)(smem + 2 * XH_BYTES + YF_BYTES) };
    __half* Ws  = (__half*)(smem + 2 * XH_BYTES + 2 * YF_BYTES);
    __half* W1s = Ws + H * WLH;

    const int tid  = threadIdx.x;
    const int lane = tid & 31;
    const int w    = tid >> 5;
    const bool prod = (w >= 16);
    const int pw   = w - 16;                 // 0..15
    const int wm   = (w & 3) * 16;
    const int wn   = (w >> 2) * 32;

    const int Gh   = gridDim.x >> 1;
    const int half = ((int)blockIdx.x >= Gh) ? 1 : 0;
    const int bidh = (int)blockIdx.x - half * Gh;

    const float* x    = half ? x_dst : x_src;
    const float* Wenc = half ? Wc    : Wp;
    const float* benc = half ? bc    : bp;
    const int    koff = half ? H     : 0;
    __half*      Aout = half ? A_dst : A_src;
    __half*      xhem = half ? xh_dst : xh_src;

    int K = 0;
    if (bidh < ntiles) K = (ntiles - 1 - bidh) / Gh + 1;

    load_wh(Ws,  Wenc,      H,     tid);
    load_wh(W1s, W1 + koff, 3 * H, tid);
    __syncthreads();

    if (!prod) {
        // ---------- consumer (tensor), 16 warps, 16x32 tiles ----------
        wmma::fragment<wmma::accumulator, 16, 16, 16, float> acc[2];
        for (int k = 0; k <= K + 1; k++) {
            if (k < K) {
                int b = k & 1;
                BSYNC(1 + b);                    // X ready
                gemm64h(Xh[b], Ws, acc, wm, wn);
                store_accf(Yf[b], acc, wm, wn);
                BARR(3 + b);                     // Y ready
            }
            int j = k - 1;
            if (j >= 0 && j < K) {
                int b = j & 1;
                BSYNC(5 + b);                    // Y' ready
                gemm64h(Xh[b], W1s, acc, wm, wn);
                store_accf(Yf[b], acc, wm, wn);
                BARR(7 + b);                     // Z ready
            }
        }
    } else {
        // ---------- producer (memory), 16 warps, 4 rows each ----------
        float4 ber = __ldg((const float4*)benc + lane);
        const float4* x4 = (const float4*)x;
        h4*           A4 = (h4*)Aout;
        h4*           xh4 = (h4*)xhem;
        for (int k = 0; k <= K + 1; k++) {
            int s = k - 2;
            if (s >= 0 && s < K) {               // store A(s) as fp16
                int b = s & 1;
                BSYNC(7 + b);
                float* Yb = Yf[b];
                int base = (bidh + s * Gh) * BM;
                #pragma unroll
                for (int it = 0; it < 4; it++) {
                    int m = pw + it * 16;
                    int n = base + m;
                    if (n < n_nodes)
                        A4[(size_t)n * 32 + lane] =
                            f4_to_h4(*(float4*)(Yb + m * XLD + lane * 4));
                }
            }
            if (k < K) {                         // gather X(k) + fp16 mirror + prefetch
                int b = k & 1;
                __half* Xb = Xh[b];
                int base  = (bidh + k * Gh) * BM;
                int basen = (bidh + (k + 1) * Gh) * BM;
                bool pf = ((k + 1) < K) && ((lane & 7) == 0);
                #pragma unroll
                for (int it = 0; it < 4; it++) {
                    int m = pw + it * 16;
                    int n = base + m; if (n >= n_nodes) n = n_nodes - 1;
                    float4 v = __ldg(x4 + (size_t)n * 32 + lane);
                    if (pf) {
                        int nn = basen + m; if (nn >= n_nodes) nn = n_nodes - 1;
                        pf_l2(x4 + (size_t)nn * 32 + lane);
                    }
                    h4 hv = f4_to_h4(v);
                    *(h4*)(Xb + m * XLH + lane * 4) = hv;
                    xh4[(size_t)n * 32 + lane] = hv;   // fp16 mirror for edge kernel
                }
                BARR(1 + b);
            }
            int e = k - 1;
            if (e >= 0 && e < K) {               // epilogue(e): bias + lrelu
                int b = e & 1;
                BSYNC(3 + b);
                float*  Yb = Yf[b];
                __half* Xb = Xh[b];
                #pragma unroll
                for (int it = 0; it < 4; it++) {
                    int m = pw + it * 16;
                    float4 v = *(float4*)(Yb + m * XLD + lane * 4);
                    v.x += ber.x; v.y += ber.y; v.z += ber.z; v.w += ber.w;
                    v.x = (v.x > 0.f) ? v.x : 0.01f * v.x;
                    v.y = (v.y > 0.f) ? v.y : 0.01f * v.y;
                    v.z = (v.z > 0.f) ? v.z : 0.01f * v.z;
                    v.w = (v.w > 0.f) ? v.w : 0.01f * v.w;
                    st_half4(Xb + m * XLH + lane * 4, v);
                }
                BARR(5 + b);
            }
        }
    }
}

// =====================================================================
// EDGE kernel: out[e] = relu(|p-c|@W1d^T + A_src[si] + A_dst[di] + b1) @ W2^T + b2
// All gathers read fp16 rows (256B). Warps 0-15 tensor, 16-31 memory.
// 4-deep idx slots staged 2 ahead; L2 prefetch one stage before use.
// =====================================================================
__global__ void __launch_bounds__(NTHREADS, 1)
edge_kernel(const __half* __restrict__ xh_src, const __half* __restrict__ xh_dst,
            const void* __restrict__ ei,
            const float* __restrict__ W1, const float* __restrict__ b1,
            const float* __restrict__ W2, const float* __restrict__ b2,
            const __half* __restrict__ A_src, const __half* __restrict__ A_dst,
            float* __restrict__ out, int n_edges, int ntiles)
{
    extern __shared__ char smem[];
    __half* Xh[2] = { (__half*)smem, (__half*)(smem + XH_BYTES) };
    float*  Yf[2] = { (float*)(smem + 2 * XH_BYTES),
                      (float*)(smem + 2 * XH_BYTES + YF_BYTES) };
    __half* W1s = (__half*)(smem + 2 * XH_BYTES + 2 * YF_BYTES);
    __half* W2s = W1s + H * WLH;
    __shared__ int s_si[4][BM], s_di[4][BM];
    __shared__ int s_flag;

    const int tid  = threadIdx.x;
    const int lane = tid & 31;
    const int w    = tid >> 5;
    const bool prod = (w >= 16);
    const int pw   = w - 16;                 // 0..15
    const int wm   = (w & 3) * 16;
    const int wn   = (w >> 2) * 32;
    const int G    = gridDim.x;

    int K = 0;
    if ((int)blockIdx.x < ntiles) K = (ntiles - 1 - (int)blockIdx.x) / G + 1;

    // inline int32/int64 detection
    if (tid == 0) s_flag = 0;
    __syncthreads();
    if (tid < 64 && ((const int*)ei)[tid * 2 + 1] != 0) atomicOr(&s_flag, 1);

    load_wh(W1s, W1 + 2 * H, 3 * H, tid);
    load_wh(W2s, W2,         H,     tid);
    __syncthreads();
    const int is64 = s_flag ? 0 : 1;

    // preload indices of tiles 0 and 1
    if (K > 0 && tid < BM) {
        int e = (int)blockIdx.x * BM + tid; if (e >= n_edges) e = n_edges - 1;
        if (is64) {
            s_si[0][tid] = (int)((const long long*)ei)[e];
            s_di[0][tid] = (int)((const long long*)ei)[(size_t)n_edges + e];
        } else {
            s_si[0][tid] = ((const int*)ei)[e];
            s_di[0][tid] = ((const int*)ei)[(size_t)n_edges + e];
        }
    }
    if (K > 1 && tid < BM) {
        int e = ((int)blockIdx.x + G) * BM + tid; if (e >= n_edges) e = n_edges - 1;
        if (is64) {
            s_si[1][tid] = (int)((const long long*)ei)[e];
            s_di[1][tid] = (int)((const long long*)ei)[(size_t)n_edges + e];
        } else {
            s_si[1][tid] = ((const int*)ei)[e];
            s_di[1][tid] = ((const int*)ei)[(size_t)n_edges + e];
        }
    }
    __syncthreads();

    if (!prod) {
        // ---------- consumer (tensor), 16 warps, 16x32 tiles ----------
        wmma::fragment<wmma::accumulator, 16, 16, 16, float> acc[2];
        for (int k = 0; k <= K + 1; k++) {
            if (k < K) {
                int b = k & 1;
                BSYNC(1 + b);                    // diff ready
                gemm64h(Xh[b], W1s, acc, wm, wn);
                store_accf(Yf[b], acc, wm, wn);
                BARR(3 + b);                     // Y ready
            }
            int j = k - 1;
            if (j >= 0 && j < K) {
                int b = j & 1;
                BSYNC(5 + b);                    // Y' ready
                gemm64h(Xh[b], W2s, acc, wm, wn);
                store_accf(Yf[b], acc, wm, wn);
                BARR(7 + b);                     // Z ready
            }
        }
    } else {
        // ---------- producer (memory), 16 warps, 4 rows each ----------
        float4 b1r = __ldg((const float4*)b1 + lane);
        float4 b2r = __ldg((const float4*)b2 + lane);
        const h4* src4 = (const h4*)xh_src;
        const h4* dst4 = (const h4*)xh_dst;
        const h4* As4  = (const h4*)A_src;
        const h4* Ad4  = (const h4*)A_dst;
        float4*   out4 = (float4*)out;
        const int ptid = tid - 512;              // 0..511

        for (int k = 0; k <= K + 1; k++) {
            int s = k - 2;
            if (s >= 0 && s < K) {                   // store out(s)
                int b = s & 1;
                BSYNC(7 + b);
                float* Yb = Yf[b];
                int base = ((int)blockIdx.x + s * G) * BM;
                #pragma unroll
                for (int it = 0; it < 4; it++) {
                    int m = pw + it * 16;
                    int e = base + m;
                    if (e < n_edges) {
                        float4 v = *(float4*)(Yb + m * XLD + lane * 4);
                        v.x += b2r.x; v.y += b2r.y; v.z += b2r.z; v.w += b2r.w;
                        __stcs(out4 + (size_t)e * 32 + lane, v);
                    }
                }
            }
            if (k < K) {                             // gather diff(k): fp16 rows
                int b = k & 1;
                const int ib = k & 3;
                __half* Xb = Xh[b];
                #pragma unroll
                for (int it = 0; it < 4; it++) {
                    int m  = pw + it * 16;
                    int si = s_si[ib][m], di = s_di[ib][m];
                    h4 p = ldg_h4(src4 + (size_t)si * 32 + lane);
                    h4 c = ldg_h4(dst4 + (size_t)di * 32 + lane);
                    h4 d;
                    d.a = __habs2(__hsub2(p.a, c.a));
                    d.b = __habs2(__hsub2(p.b, c.b));
                    *(h4*)(Xb + m * XLH + lane * 4) = d;
                }
                BARR(1 + b);
            }
            int e = k - 1;
            if (e >= 0 && e < K) {                   // epilogue(e): +A+b1, relu
                int b = e & 1;
                const int ib = e & 3;
                BSYNC(3 + b);
                float*  Yb = Yf[b];
                __half* Xb = Xh[b];
                #pragma unroll
                for (int it = 0; it < 4; it++) {
                    int m  = pw + it * 16;
                    int si = s_si[ib][m], di = s_di[ib][m];
                    float4 as = h4_to_f4(ldg_h4(As4 + (size_t)si * 32 + lane));
                    float4 ad = h4_to_f4(ldg_h4(Ad4 + (size_t)di * 32 + lane));
                    float4 v  = *(float4*)(Yb + m * XLD + lane * 4);
                    v.x = fmaxf(v.x + as.x + ad.x + b1r.x, 0.f);
                    v.y = fmaxf(v.y + as.y + ad.y + b1r.y, 0.f);
                    v.z = fmaxf(v.z + as.z + ad.z + b1r.z, 0.f);
                    v.w = fmaxf(v.w + as.w + ad.w + b1r.w, 0.f);
                    st_half4(Xb + m * XLH + lane * 4, v);
                }
                BARR(5 + b);
            }
            if (k + 2 < K && ptid < BM) {            // stage idx(k+2)
                int tn = (int)blockIdx.x + (k + 2) * G;
                int ee = tn * BM + ptid; if (ee >= n_edges) ee = n_edges - 1;
                const int ib = (k + 2) & 3;
                if (is64) {
                    s_si[ib][ptid] = (int)((const long long*)ei)[ee];
                    s_di[ib][ptid] = (int)((const long long*)ei)[(size_t)n_edges + ee];
                } else {
                    s_si[ib][ptid] = ((const int*)ei)[ee];
                    s_di[ib][ptid] = ((const int*)ei)[(size_t)n_edges + ee];
                }
            }
            if (k + 1 < K && ptid < BM) {            // prefetch tile k+1 rows (2 lines each)
                const int ib = (k + 1) & 3;
                size_t si = (size_t)s_si[ib][ptid] * 32;
                size_t di = (size_t)s_di[ib][ptid] * 32;
                pf_l2(src4 + si);      pf_l2(src4 + si + 16);
                pf_l2(dst4 + di);      pf_l2(dst4 + di + 16);
                pf_l2(As4  + si);      pf_l2(As4  + si + 16);
                pf_l2(Ad4  + di);      pf_l2(Ad4  + di + 16);
            }
        }
    }
}

// ---------------- launch ----------------
extern "C" void kernel_launch(void* const* d_in, const int* in_sizes, int n_in,
                              void* d_out, int out_size)
{
    const float* x_src = (const float*)d_in[0];
    const float* x_dst = (const float*)d_in[1];
    const void*  ei    = d_in[2];
    const float* Wp    = (const float*)d_in[3];
    const float* bp    = (const float*)d_in[4];
    const float* Wc    = (const float*)d_in[5];
    const float* bc    = (const float*)d_in[6];
    const float* W1    = (const float*)d_in[7];
    const float* b1    = (const float*)d_in[8];
    const float* W2    = (const float*)d_in[9];
    const float* b2    = (const float*)d_in[10];

    const int n_nodes = in_sizes[0] / H;
    const int n_edges = in_sizes[2] / 2;

    static int attr_set = 0;
    if (!attr_set) {
        cudaFuncSetAttribute(node_kernel, cudaFuncAttributeMaxDynamicSharedMemorySize, SMEM_BYTES);
        cudaFuncSetAttribute(edge_kernel, cudaFuncAttributeMaxDynamicSharedMemorySize, SMEM_BYTES);
        attr_set = 1;
    }

    __half *xh_s, *xh_d, *A_s, *A_d;
    cudaGetSymbolAddress((void**)&xh_s, g_xh_src);
    cudaGetSymbolAddress((void**)&xh_d, g_xh_dst);
    cudaGetSymbolAddress((void**)&A_s,  g_A_src);
    cudaGetSymbolAddress((void**)&A_d,  g_A_dst);

    const int node_tiles = (n_nodes + BM - 1) / BM;   // per half
    int ngrid = 2 * (node_tiles < NSM ? node_tiles : NSM);
    if (ngrid > NSM) ngrid = NSM;        // 152 CTAs: 76 per half
    if (ngrid < 2) ngrid = 2;
    ngrid &= ~1;                          // even
    node_kernel<<<ngrid, NTHREADS, SMEM_BYTES>>>(
        x_src, x_dst, Wp, bp, Wc, bc, W1, xh_s, xh_d, A_s, A_d, n_nodes, node_tiles);

    const int edge_tiles = (n_edges + BM - 1) / BM;
    const int egrid = edge_tiles < NSM ? edge_tiles : NSM;
    edge_kernel<<<egrid, NTHREADS, SMEM_BYTES>>>(
        xh_s, xh_d, ei, W1, b1, W2, b2, A_s, A_d, (float*)d_out, n_edges, edge_tiles);
}

// round 17
// speedup vs baseline: 1.3256x; 1.3256x over previous
#include <cuda_runtime.h>
#include <cstdint>
#include <mma.h>
#include <cuda_fp16.h>
#include <math.h>

using namespace nvcuda;

#define H        128
#define BM       64       // rows per tile
#define XLH      136      // half leading dim for input tiles (8-half pad)
#define WLH      136      // half leading dim for weights
#define XLD      132      // float leading dim for accum buffer
#define NTHREADS 768      // 8 consumer warps + 16 producer warps
#define NSM      152

#define XH_BYTES (BM * XLH * 2)          // 17408
#define YF_BYTES (BM * XLD * 4)          // 33792
#define WH_BYTES (H * WLH * 2)           // 34816
#define SMEM_BYTES (2 * XH_BYTES + 2 * YF_BYTES + 2 * WH_BYTES)   // 172032

// ---------------- scratch (fp16 mirrors + fp16 A) ----------------
#define MAX_NODES 100000
__device__ __half g_xh_src[(size_t)MAX_NODES * H];
__device__ __half g_xh_dst[(size_t)MAX_NODES * H];
__device__ __half g_A_src[(size_t)MAX_NODES * H];
__device__ __half g_A_dst[(size_t)MAX_NODES * H];

// ---------------- named barriers (768 = full CTA) ----------------
#define BSYNC(id)  asm volatile("bar.sync %0, 768;"   :: "r"(id) : "memory")
#define BARR(id)   asm volatile("bar.arrive %0, 768;" :: "r"(id) : "memory")

// ---------------- helpers ----------------
__device__ __forceinline__ void pf_l2(const void* p)
{
    asm volatile("prefetch.global.L2 [%0];" :: "l"(p));
}

struct alignas(8) h4 { __half2 a, b; };

__device__ __forceinline__ h4 ldg_h4(const h4* p)
{
    uint2 u = __ldg((const uint2*)p);
    h4 t;
    t.a = *(__half2*)&u.x;
    t.b = *(__half2*)&u.y;
    return t;
}

__device__ __forceinline__ h4 f4_to_h4(float4 v)
{
    h4 t;
    t.a = __floats2half2_rn(v.x, v.y);
    t.b = __floats2half2_rn(v.z, v.w);
    return t;
}
__device__ __forceinline__ float4 h4_to_f4(h4 t)
{
    float2 lo = __half22float2(t.a), hi = __half22float2(t.b);
    return make_float4(lo.x, lo.y, hi.x, hi.y);
}
__device__ __forceinline__ void st_half4(__half* p, float4 v)
{
    *(h4*)p = f4_to_h4(v);
}

// convert a 128x128 float weight matrix (row stride `stride`) to half in smem
__device__ __forceinline__ void load_wh(
    __half* __restrict__ Wh, const float* __restrict__ Wg, int stride, int tid)
{
    for (int idx = tid; idx < H * 32; idx += NTHREADS) {
        int j = idx >> 5, k4 = idx & 31;
        float4 v = __ldg((const float4*)(Wg + (size_t)j * stride) + k4);
        st_half4(Wh + j * WLH + k4 * 4, v);
    }
}

// 8 consumer warps on a 64x128 tile: warp w -> rows [wm,wm+32), cols [wn,wn+32)
__device__ __forceinline__ void gemm64h(
    const __half* __restrict__ Xs, const __half* __restrict__ Ws,
    wmma::fragment<wmma::accumulator, 16, 16, 16, float> (&acc)[2][2],
    int wm, int wn)
{
    #pragma unroll
    for (int i = 0; i < 2; i++)
        #pragma unroll
        for (int j = 0; j < 2; j++)
            wmma::fill_fragment(acc[i][j], 0.0f);

    #pragma unroll
    for (int k0 = 0; k0 < H; k0 += 16) {
        wmma::fragment<wmma::matrix_a, 16, 16, 16, __half, wmma::row_major> a[2];
        wmma::fragment<wmma::matrix_b, 16, 16, 16, __half, wmma::col_major> b[2];
        #pragma unroll
        for (int i = 0; i < 2; i++)
            wmma::load_matrix_sync(a[i], Xs + (wm + i * 16) * XLH + k0, XLH);
        #pragma unroll
        for (int j = 0; j < 2; j++)
            wmma::load_matrix_sync(b[j], Ws + (wn + j * 16) * WLH + k0, WLH);
        #pragma unroll
        for (int i = 0; i < 2; i++)
            #pragma unroll
            for (int j = 0; j < 2; j++)
                wmma::mma_sync(acc[i][j], a[i], b[j], acc[i][j]);
    }
}

__device__ __forceinline__ void store_accf(
    float* __restrict__ Yf,
    wmma::fragment<wmma::accumulator, 16, 16, 16, float> (&acc)[2][2],
    int wm, int wn)
{
    #pragma unroll
    for (int i = 0; i < 2; i++)
        #pragma unroll
        for (int j = 0; j < 2; j++)
            wmma::store_matrix_sync(Yf + (wm + i * 16) * XLD + wn + j * 16,
                                    acc[i][j], XLD, wmma::mem_row_major);
}

// =====================================================================
// NODE kernel: A[n] = (leakyrelu(x @ Wenc^T + benc)) @ W1slab^T
// Also emits fp16 mirrors of x; A stored as fp16. Grid-split halves.
// Warps 0-7 tensor, 8-23 memory.  (identical to R15)
// =====================================================================
__global__ void __launch_bounds__(NTHREADS, 1)
node_kernel(const float* __restrict__ x_src, const float* __restrict__ x_dst,
            const float* __restrict__ Wp, const float* __restrict__ bp,
            const float* __restrict__ Wc, const float* __restrict__ bc,
            const float* __restrict__ W1,
            __half* __restrict__ xh_src, __half* __restrict__ xh_dst,
            __half* __restrict__ A_src, __half* __restrict__ A_dst,
            int n_nodes, int ntiles)
{
    extern __shared__ char smem[];
    __half* Xh[2] = { (__half*)smem, (__half*)(smem + XH_BYTES) };
    float*  Yf[2] = { (float*)(smem + 2 * XH_BYTES),
                      (float*)(smem + 2 * XH_BYTES + YF_BYTES) };
    __half* Ws  = (__half*)(smem + 2 * XH_BYTES + 2 * YF_BYTES);
    __half* W1s = Ws + H * WLH;

    const int tid  = threadIdx.x;
    const int lane = tid & 31;
    const int w    = tid >> 5;
    const bool prod = (w >= 8);
    const int pw   = w - 8;                  // 0..15
    const int wm   = (w & 1) * 32;
    const int wn   = (w >> 1) * 32;

    const int Gh   = gridDim.x >> 1;
    const int half = ((int)blockIdx.x >= Gh) ? 1 : 0;
    const int bidh = (int)blockIdx.x - half * Gh;

    const float* x    = half ? x_dst : x_src;
    const float* Wenc = half ? Wc    : Wp;
    const float* benc = half ? bc    : bp;
    const int    koff = half ? H     : 0;
    __half*      Aout = half ? A_dst : A_src;
    __half*      xhem = half ? xh_dst : xh_src;

    int K = 0;
    if (bidh < ntiles) K = (ntiles - 1 - bidh) / Gh + 1;

    load_wh(Ws,  Wenc,      H,     tid);
    load_wh(W1s, W1 + koff, 3 * H, tid);
    __syncthreads();

    if (!prod) {
        // ---------- consumer (tensor) ----------
        wmma::fragment<wmma::accumulator, 16, 16, 16, float> acc[2][2];
        for (int k = 0; k <= K + 1; k++) {
            if (k < K) {
                int b = k & 1;
                BSYNC(1 + b);                    // X ready
                gemm64h(Xh[b], Ws, acc, wm, wn);
                store_accf(Yf[b], acc, wm, wn);
                BARR(3 + b);                     // Y ready
            }
            int j = k - 1;
            if (j >= 0 && j < K) {
                int b = j & 1;
                BSYNC(5 + b);                    // Y' ready
                gemm64h(Xh[b], W1s, acc, wm, wn);
                store_accf(Yf[b], acc, wm, wn);
                BARR(7 + b);                     // Z ready
            }
        }
    } else {
        // ---------- producer (memory), 16 warps, 4 rows each ----------
        float4 ber = __ldg((const float4*)benc + lane);
        const float4* x4 = (const float4*)x;
        h4*           A4 = (h4*)Aout;
        h4*           xh4 = (h4*)xhem;
        for (int k = 0; k <= K + 1; k++) {
            int s = k - 2;
            if (s >= 0 && s < K) {               // store A(s) as fp16
                int b = s & 1;
                BSYNC(7 + b);
                float* Yb = Yf[b];
                int base = (bidh + s * Gh) * BM;
                #pragma unroll
                for (int it = 0; it < 4; it++) {
                    int m = pw + it * 16;
                    int n = base + m;
                    if (n < n_nodes)
                        A4[(size_t)n * 32 + lane] =
                            f4_to_h4(*(float4*)(Yb + m * XLD + lane * 4));
                }
            }
            if (k < K) {                         // gather X(k) + fp16 mirror + prefetch
                int b = k & 1;
                __half* Xb = Xh[b];
                int base  = (bidh + k * Gh) * BM;
                int basen = (bidh + (k + 1) * Gh) * BM;
                bool pf = ((k + 1) < K) && ((lane & 7) == 0);
                #pragma unroll
                for (int it = 0; it < 4; it++) {
                    int m = pw + it * 16;
                    int n = base + m; if (n >= n_nodes) n = n_nodes - 1;
                    float4 v = __ldg(x4 + (size_t)n * 32 + lane);
                    if (pf) {
                        int nn = basen + m; if (nn >= n_nodes) nn = n_nodes - 1;
                        pf_l2(x4 + (size_t)nn * 32 + lane);
                    }
                    h4 hv = f4_to_h4(v);
                    *(h4*)(Xb + m * XLH + lane * 4) = hv;
                    xh4[(size_t)n * 32 + lane] = hv;   // fp16 mirror for edge kernel
                }
                BARR(1 + b);
            }
            int e = k - 1;
            if (e >= 0 && e < K) {               // epilogue(e): bias + lrelu
                int b = e & 1;
                BSYNC(3 + b);
                float*  Yb = Yf[b];
                __half* Xb = Xh[b];
                #pragma unroll
                for (int it = 0; it < 4; it++) {
                    int m = pw + it * 16;
                    float4 v = *(float4*)(Yb + m * XLD + lane * 4);
                    v.x += ber.x; v.y += ber.y; v.z += ber.z; v.w += ber.w;
                    v.x = (v.x > 0.f) ? v.x : 0.01f * v.x;
                    v.y = (v.y > 0.f) ? v.y : 0.01f * v.y;
                    v.z = (v.z > 0.f) ? v.z : 0.01f * v.z;
                    v.w = (v.w > 0.f) ? v.w : 0.01f * v.w;
                    st_half4(Xb + m * XLH + lane * 4, v);
                }
                BARR(5 + b);
            }
        }
    }
}

// =====================================================================
// EDGE kernel: out[e] = relu(|p-c|@W1d^T + A_src[si] + A_dst[di] + b1) @ W2^T + b2
// Producer phase order: store -> epilogue -> gather. A rows for tile k are
// loaded into REGISTERS during gather(k) and consumed by epilogue(k) one
// iteration later (before gather(k+1) overwrites them) — the loads get the
// whole GEMM1 to land, making the epilogue pure ALU.
// =====================================================================
__global__ void __launch_bounds__(NTHREADS, 1)
edge_kernel(const __half* __restrict__ xh_src, const __half* __restrict__ xh_dst,
            const void* __restrict__ ei,
            const float* __restrict__ W1, const float* __restrict__ b1,
            const float* __restrict__ W2, const float* __restrict__ b2,
            const __half* __restrict__ A_src, const __half* __restrict__ A_dst,
            float* __restrict__ out, int n_edges, int ntiles)
{
    extern __shared__ char smem[];
    __half* Xh[2] = { (__half*)smem, (__half*)(smem + XH_BYTES) };
    float*  Yf[2] = { (float*)(smem + 2 * XH_BYTES),
                      (float*)(smem + 2 * XH_BYTES + YF_BYTES) };
    __half* W1s = (__half*)(smem + 2 * XH_BYTES + 2 * YF_BYTES);
    __half* W2s = W1s + H * WLH;
    __shared__ int s_si[4][BM], s_di[4][BM];
    __shared__ int s_flag;

    const int tid  = threadIdx.x;
    const int lane = tid & 31;
    const int w    = tid >> 5;
    const bool prod = (w >= 8);
    const int pw   = w - 8;                  // 0..15
    const int wm   = (w & 1) * 32;
    const int wn   = (w >> 1) * 32;
    const int G    = gridDim.x;

    int K = 0;
    if ((int)blockIdx.x < ntiles) K = (ntiles - 1 - (int)blockIdx.x) / G + 1;

    // inline int32/int64 detection
    if (tid == 0) s_flag = 0;
    __syncthreads();
    if (tid < 64 && ((const int*)ei)[tid * 2 + 1] != 0) atomicOr(&s_flag, 1);

    load_wh(W1s, W1 + 2 * H, 3 * H, tid);
    load_wh(W2s, W2,         H,     tid);
    __syncthreads();
    const int is64 = s_flag ? 0 : 1;

    // preload indices of tiles 0 and 1
    if (K > 0 && tid < BM) {
        int e = (int)blockIdx.x * BM + tid; if (e >= n_edges) e = n_edges - 1;
        if (is64) {
            s_si[0][tid] = (int)((const long long*)ei)[e];
            s_di[0][tid] = (int)((const long long*)ei)[(size_t)n_edges + e];
        } else {
            s_si[0][tid] = ((const int*)ei)[e];
            s_di[0][tid] = ((const int*)ei)[(size_t)n_edges + e];
        }
    }
    if (K > 1 && tid < BM) {
        int e = ((int)blockIdx.x + G) * BM + tid; if (e >= n_edges) e = n_edges - 1;
        if (is64) {
            s_si[1][tid] = (int)((const long long*)ei)[e];
            s_di[1][tid] = (int)((const long long*)ei)[(size_t)n_edges + e];
        } else {
            s_si[1][tid] = ((const int*)ei)[e];
            s_di[1][tid] = ((const int*)ei)[(size_t)n_edges + e];
        }
    }
    __syncthreads();

    if (!prod) {
        // ---------- consumer (tensor) ----------
        wmma::fragment<wmma::accumulator, 16, 16, 16, float> acc[2][2];
        for (int k = 0; k <= K + 1; k++) {
            if (k < K) {
                int b = k & 1;
                BSYNC(1 + b);                    // diff ready
                gemm64h(Xh[b], W1s, acc, wm, wn);
                store_accf(Yf[b], acc, wm, wn);
                BARR(3 + b);                     // Y ready
            }
            int j = k - 1;
            if (j >= 0 && j < K) {
                int b = j & 1;
                BSYNC(5 + b);                    // Y' ready
                gemm64h(Xh[b], W2s, acc, wm, wn);
                store_accf(Yf[b], acc, wm, wn);
                BARR(7 + b);                     // Z ready
            }
        }
    } else {
        // ---------- producer (memory), 16 warps, 4 rows each ----------
        float4 b1r = __ldg((const float4*)b1 + lane);
        float4 b2r = __ldg((const float4*)b2 + lane);
        const h4* src4 = (const h4*)xh_src;
        const h4* dst4 = (const h4*)xh_dst;
        const h4* As4  = (const h4*)A_src;
        const h4* Ad4  = (const h4*)A_dst;
        float4*   out4 = (float4*)out;
        const int ptid = tid - 256;              // 0..511

        h4 as_r[4], ad_r[4];                     // A rows for in-flight tile

        for (int k = 0; k <= K + 1; k++) {
            int s = k - 2;
            if (s >= 0 && s < K) {                   // store out(s)
                int b = s & 1;
                BSYNC(7 + b);
                float* Yb = Yf[b];
                int base = ((int)blockIdx.x + s * G) * BM;
                #pragma unroll
                for (int it = 0; it < 4; it++) {
                    int m = pw + it * 16;
                    int e = base + m;
                    if (e < n_edges) {
                        float4 v = *(float4*)(Yb + m * XLD + lane * 4);
                        v.x += b2r.x; v.y += b2r.y; v.z += b2r.z; v.w += b2r.w;
                        __stcs(out4 + (size_t)e * 32 + lane, v);
                    }
                }
            }
            int e = k - 1;
            if (e >= 0 && e < K) {                   // epilogue(e): regs + b1, relu
                int b = e & 1;
                BSYNC(3 + b);
                float*  Yb = Yf[b];
                __half* Xb = Xh[b];
                #pragma unroll
                for (int it = 0; it < 4; it++) {
                    int m  = pw + it * 16;
                    float4 as = h4_to_f4(as_r[it]);
                    float4 ad = h4_to_f4(ad_r[it]);
                    float4 v  = *(float4*)(Yb + m * XLD + lane * 4);
                    v.x = fmaxf(v.x + as.x + ad.x + b1r.x, 0.f);
                    v.y = fmaxf(v.y + as.y + ad.y + b1r.y, 0.f);
                    v.z = fmaxf(v.z + as.z + ad.z + b1r.z, 0.f);
                    v.w = fmaxf(v.w + as.w + ad.w + b1r.w, 0.f);
                    st_half4(Xb + m * XLH + lane * 4, v);
                }
                BARR(5 + b);
            }
            if (k < K) {                             // gather diff(k) + A rows into regs
                int b = k & 1;
                const int ib = k & 3;
                __half* Xb = Xh[b];
                #pragma unroll
                for (int it = 0; it < 4; it++) {
                    int m  = pw + it * 16;
                    int si = s_si[ib][m], di = s_di[ib][m];
                    h4 p = ldg_h4(src4 + (size_t)si * 32 + lane);
                    h4 c = ldg_h4(dst4 + (size_t)di * 32 + lane);
                    as_r[it] = ldg_h4(As4 + (size_t)si * 32 + lane);
                    ad_r[it] = ldg_h4(Ad4 + (size_t)di * 32 + lane);
                    h4 d;
                    d.a = __habs2(__hsub2(p.a, c.a));
                    d.b = __habs2(__hsub2(p.b, c.b));
                    *(h4*)(Xb + m * XLH + lane * 4) = d;
                }
                BARR(1 + b);
            }
            if (k + 2 < K && ptid < BM) {            // stage idx(k+2)
                int tn = (int)blockIdx.x + (k + 2) * G;
                int ee = tn * BM + ptid; if (ee >= n_edges) ee = n_edges - 1;
                const int ib = (k + 2) & 3;
                if (is64) {
                    s_si[ib][ptid] = (int)((const long long*)ei)[ee];
                    s_di[ib][ptid] = (int)((const long long*)ei)[(size_t)n_edges + ee];
                } else {
                    s_si[ib][ptid] = ((const int*)ei)[ee];
                    s_di[ib][ptid] = ((const int*)ei)[(size_t)n_edges + ee];
                }
            }
            if (k + 1 < K && ptid < BM) {            // prefetch next tile's x rows
                const int ib = (k + 1) & 3;
                size_t si = (size_t)s_si[ib][ptid] * 32;
                size_t di = (size_t)s_di[ib][ptid] * 32;
                pf_l2(src4 + si);      pf_l2(src4 + si + 16);
                pf_l2(dst4 + di);      pf_l2(dst4 + di + 16);
                pf_l2(As4  + si);      pf_l2(As4  + si + 16);
                pf_l2(Ad4  + di);      pf_l2(Ad4  + di + 16);
            }
        }
    }
}

// ---------------- launch ----------------
extern "C" void kernel_launch(void* const* d_in, const int* in_sizes, int n_in,
                              void* d_out, int out_size)
{
    const float* x_src = (const float*)d_in[0];
    const float* x_dst = (const float*)d_in[1];
    const void*  ei    = d_in[2];
    const float* Wp    = (const float*)d_in[3];
    const float* bp    = (const float*)d_in[4];
    const float* Wc    = (const float*)d_in[5];
    const float* bc    = (const float*)d_in[6];
    const float* W1    = (const float*)d_in[7];
    const float* b1    = (const float*)d_in[8];
    const float* W2    = (const float*)d_in[9];
    const float* b2    = (const float*)d_in[10];

    const int n_nodes = in_sizes[0] / H;
    const int n_edges = in_sizes[2] / 2;

    static int attr_set = 0;
    if (!attr_set) {
        cudaFuncSetAttribute(node_kernel, cudaFuncAttributeMaxDynamicSharedMemorySize, SMEM_BYTES);
        cudaFuncSetAttribute(edge_kernel, cudaFuncAttributeMaxDynamicSharedMemorySize, SMEM_BYTES);
        attr_set = 1;
    }

    __half *xh_s, *xh_d, *A_s, *A_d;
    cudaGetSymbolAddress((void**)&xh_s, g_xh_src);
    cudaGetSymbolAddress((void**)&xh_d, g_xh_dst);
    cudaGetSymbolAddress((void**)&A_s,  g_A_src);
    cudaGetSymbolAddress((void**)&A_d,  g_A_dst);

    const int node_tiles = (n_nodes + BM - 1) / BM;   // per half
    int ngrid = 2 * (node_tiles < NSM ? node_tiles : NSM);
    if (ngrid > NSM) ngrid = NSM;        // 152 CTAs: 76 per half
    if (ngrid < 2) ngrid = 2;
    ngrid &= ~1;                          // even
    node_kernel<<<ngrid, NTHREADS, SMEM_BYTES>>>(
        x_src, x_dst, Wp, bp, Wc, bc, W1, xh_s, xh_d, A_s, A_d, n_nodes, node_tiles);

    const int edge_tiles = (n_edges + BM - 1) / BM;
    const int egrid = edge_tiles < NSM ? edge_tiles : NSM;
    edge_kernel<<<egrid, NTHREADS, SMEM_BYTES>>>(
        xh_s, xh_d, ei, W1, b1, W2, b2, A_s, A_d, (float*)d_out, n_edges, edge_tiles);
}